// round 11
// baseline (speedup 1.0000x reference)
#include <cuda_runtime.h>
#include <cuda_bf16.h>

#define BATCH  32
#define T_     3749            // num frames per row
#define CROW   3750            // chunks per row
#define NCHUNK (BATCH*CROW)    // 120000
#define NBLK   148
#define TILE   811             // ceil(NCHUNK/NBLK)
#define SILF   18
#define MINSP  6
#define WN32   120             // mask words storage (padded)
#define NWORDS 118             // ceil(3749/32)
#define HB1    4096            // pass-1 bins (top 12 bits)
#define MAXG   256

__device__ float    g_E[BATCH * T_];
__device__ int      g_hist[BATCH * HB1];  // zero at load; phase 2 restores zeros
__device__ int      g_nzero[BATCH];       // zero at load; phase 2 restores zeros
__device__ unsigned g_count;
__device__ unsigned g_epoch;

__device__ __forceinline__ void grid_barrier() {
    __syncthreads();
    if (threadIdx.x == 0) {
        unsigned e0 = *((volatile unsigned*)&g_epoch);
        __threadfence();
        unsigned a = atomicAdd(&g_count, 1u);
        if (a == NBLK - 1) {
            g_count = 0;
            __threadfence();
            atomicAdd(&g_epoch, 1u);
        } else {
            while (*((volatile unsigned*)&g_epoch) == e0) { }
        }
        __threadfence();
    }
    __syncthreads();
}

__device__ __forceinline__ int warp_incl_scan(int x, int lane) {
    #pragma unroll
    for (int o = 1; o < 32; o <<= 1) {
        int y = __shfl_up_sync(0xFFFFFFFFu, x, o);
        if (lane >= o) x += y;
    }
    return x;
}
__device__ __forceinline__ int block_excl_scan(int v, int lane, int wid, int* warp_sums) {
    int x = warp_incl_scan(v, lane);
    if (lane == 31) warp_sums[wid] = x;
    __syncthreads();
    if (wid == 0) {
        int ws = warp_sums[lane];
        int xx = warp_incl_scan(ws, lane);
        warp_sums[lane] = xx - ws;
    }
    __syncthreads();
    int res = warp_sums[wid] + x - v;
    __syncthreads();
    return res;
}

__global__ __launch_bounds__(1024, 1)
void vad_fused_kernel(const float* __restrict__ W, float* __restrict__ out, int n_samples) {
    int tid = threadIdx.x, lane = tid & 31, wid = tid >> 5;

    __shared__ float    s_sum[TILE + 1];
    __shared__ int      hist_s[2048];            // dual regions: lo [0..1023], hi [1024..2047]
    __shared__ unsigned mword[WN32];
    __shared__ short    llist[MAXG];
    __shared__ short    vs_s[MAXG];
    __shared__ short    ve_s[MAXG];
    __shared__ int      warp_sums[32];
    __shared__ int      rlo_sh, rhi_sh;
    __shared__ unsigned plo_sh, phi_sh;
    __shared__ int      G_sh;

    // ===== Phase 1: depth-3 pipelined chunk sums -> energies + hist + nzero =====
    int s0   = blockIdx.x * TILE;
    int len  = min(TILE, NCHUNK - s0);
    int nsum = min(len + 1, NCHUNK - s0);

    {
        float4 a0={0,0,0,0}, b0={0,0,0,0}, a1={0,0,0,0}, b1={0,0,0,0};
        int j = wid;
        if (j < nsum) {
            int c = s0 + j; int r = c / CROW, jj = c - r * CROW;
            const float4* p = (const float4*)(W + (size_t)r * n_samples) + (size_t)jj * 64;
            a0 = __ldcs(p + lane); b0 = __ldcs(p + lane + 32);
        }
        if (j + 32 < nsum) {
            int c = s0 + j + 32; int r = c / CROW, jj = c - r * CROW;
            const float4* p = (const float4*)(W + (size_t)r * n_samples) + (size_t)jj * 64;
            a1 = __ldcs(p + lane); b1 = __ldcs(p + lane + 32);
        }
        for (; j < nsum; j += 32) {
            float4 a2={0,0,0,0}, b2={0,0,0,0};
            if (j + 64 < nsum) {
                int c = s0 + j + 64; int r = c / CROW, jj = c - r * CROW;
                const float4* p = (const float4*)(W + (size_t)r * n_samples) + (size_t)jj * 64;
                a2 = __ldcs(p + lane); b2 = __ldcs(p + lane + 32);
            }
            float v = a0.x*a0.x + a0.y*a0.y + a0.z*a0.z + a0.w*a0.w
                    + b0.x*b0.x + b0.y*b0.y + b0.z*b0.z + b0.w*b0.w;
            #pragma unroll
            for (int o = 16; o; o >>= 1) v += __shfl_down_sync(0xFFFFFFFFu, v, o);
            if (lane == 0) s_sum[j] = v;
            a0 = a1; b0 = b1; a1 = a2; b1 = b2;
        }
    }
    __syncthreads();

    {
        int i = tid;
        bool ok = (i < len);
        int rowbin = -1;
        if (ok) {
            int t = s0 + i;
            int r = t / CROW;
            int tl = t - r * CROW;
            if (tl < CROW - 1) {
                float e = (s_sum[i] + s_sum[i + 1]) * (1.0f / 512.0f);
                g_E[r * T_ + tl] = e;
                if (e <= 0.0f) atomicAdd(&g_nzero[r], 1);
                rowbin = r * HB1 + (int)(__float_as_uint(e) >> 20);
            }
        }
        unsigned grp = __match_any_sync(0xFFFFFFFFu, rowbin);
        if (rowbin >= 0 && lane == __ffs(grp) - 1)
            atomicAdd(&g_hist[rowbin], __popc(grp));
    }

    grid_barrier();

    // ===== Phase 2: per-row VAD, register-resident keys, dual-rank select =====
    if (blockIdx.x >= BATCH) return;
    int b = blockIdx.x;

    hist_s[tid] = 0; hist_s[tid + 1024] = 0;

    unsigned key[4]; bool kval[4];
    const float* Erow = g_E + b * T_;
    #pragma unroll
    for (int r = 0; r < 4; r++) {
        int i = r * 1024 + tid;
        kval[r] = (i < T_);
        key[r] = kval[r] ? __float_as_uint(Erow[i]) : 0u;
    }
    int nzero = g_nzero[b];
    int h4[4]; int base4 = tid << 2;
    #pragma unroll
    for (int j = 0; j < 4; j++) {
        h4[j] = g_hist[b * HB1 + base4 + j];
        g_hist[b * HB1 + base4 + j] = 0;
    }
    __syncthreads();
    if (tid == 0) g_nzero[b] = 0;

    int nz = T_ - nzero;
    float pos  = 0.2f * (float)(nz - 1);
    float flo  = floorf(pos);
    float frac = pos - flo;
    int ilo = min(max(nzero + (int)flo, 0), T_ - 1);
    int ihi = min(max(nzero + (int)ceilf(pos), 0), T_ - 1);

    // ---- pass 1: top-12-bit bins for BOTH ranks from precomputed hist ----
    int tsum = h4[0] + h4[1] + h4[2] + h4[3];
    int texcl = block_excl_scan(tsum, lane, wid, warp_sums);
    {
        int cum = texcl;
        #pragma unroll
        for (int j = 0; j < 4; j++) {
            if (ilo >= cum && ilo < cum + h4[j]) { rlo_sh = ilo - cum; plo_sh = (unsigned)(base4 + j) << 20; }
            if (ihi >= cum && ihi < cum + h4[j]) { rhi_sh = ihi - cum; phi_sh = (unsigned)(base4 + j) << 20; }
            cum += h4[j];
        }
    }
    __syncthreads();
    unsigned plo = plo_sh, phi = phi_sh;

    // ---- pass 2: bits 19..10, dual regions ----
    #pragma unroll
    for (int r = 0; r < 4; r++) {
        bool okl = kval[r] && ((key[r] & 0xFFF00000u) == plo);
        int binl = okl ? (int)((key[r] >> 10) & 1023u) : -1;
        unsigned gl = __match_any_sync(0xFFFFFFFFu, binl);
        if (okl && lane == __ffs(gl) - 1) atomicAdd(&hist_s[binl], __popc(gl));
        bool okh = kval[r] && ((key[r] & 0xFFF00000u) == phi);
        int binh = okh ? (int)((key[r] >> 10) & 1023u) : -1;
        unsigned gh = __match_any_sync(0xFFFFFFFFu, binh);
        if (okh && lane == __ffs(gh) - 1) atomicAdd(&hist_s[1024 + binh], __popc(gh));
    }
    __syncthreads();
    {
        int hA = hist_s[tid], hB = hist_s[tid + 1024];
        hist_s[tid] = 0; hist_s[tid + 1024] = 0;
        int rl = rlo_sh, rh = rhi_sh;
        int packed = hA | (hB << 16);
        int excl = block_excl_scan(packed, lane, wid, warp_sums);
        int exA = excl & 0xFFFF, exB = excl >> 16;
        if (rl >= exA && rl < exA + hA) { rlo_sh = rl - exA; plo_sh = plo | ((unsigned)tid << 10); }
        if (rh >= exB && rh < exB + hB) { rhi_sh = rh - exB; phi_sh = phi | ((unsigned)tid << 10); }
    }
    __syncthreads();
    plo = plo_sh; phi = phi_sh;

    // ---- pass 3: bits 9..0, dual regions -> full keys ----
    #pragma unroll
    for (int r = 0; r < 4; r++) {
        bool okl = kval[r] && ((key[r] & 0xFFFFFC00u) == plo);
        int binl = okl ? (int)(key[r] & 1023u) : -1;
        unsigned gl = __match_any_sync(0xFFFFFFFFu, binl);
        if (okl && lane == __ffs(gl) - 1) atomicAdd(&hist_s[binl], __popc(gl));
        bool okh = kval[r] && ((key[r] & 0xFFFFFC00u) == phi);
        int binh = okh ? (int)(key[r] & 1023u) : -1;
        unsigned gh = __match_any_sync(0xFFFFFFFFu, binh);
        if (okh && lane == __ffs(gh) - 1) atomicAdd(&hist_s[1024 + binh], __popc(gh));
    }
    __syncthreads();
    {
        int hA = hist_s[tid], hB = hist_s[tid + 1024];
        int rl = rlo_sh, rh = rhi_sh;
        int packed = hA | (hB << 16);
        int excl = block_excl_scan(packed, lane, wid, warp_sums);
        int exA = excl & 0xFFFF, exB = excl >> 16;
        if (rl >= exA && rl < exA + hA) plo_sh = plo | (unsigned)tid;
        if (rh >= exB && rh < exB + hB) phi_sh = phi | (unsigned)tid;
    }
    __syncthreads();
    float v_lo = __uint_as_float(plo_sh);
    float v_hi = __uint_as_float(phi_sh);
    float thr = (nz > 0) ? (v_lo * (1.0f - frac) + v_hi * frac) : 0.01f;

    // ---- mask ballot from register keys ----
    #pragma unroll
    for (int r = 0; r < 4; r++) {
        int i = r * 1024 + tid;
        bool pred = kval[r] && (__uint_as_float(key[r]) > thr);
        unsigned w = __ballot_sync(0xFFFFFFFFu, pred);
        if (lane == 0 && (i >> 5) < WN32) mword[i >> 5] = w;
    }
    __syncthreads();

    // ---- single-warp back half: flags, ordinals, intervals ----
    if (wid == 0) {
        unsigned swv[4], lwv[4];
        int scnt = 0, lcnt = 0;
        #pragma unroll
        for (int j = 0; j < 4; j++) {
            int w = lane * 4 + j;
            unsigned sw = 0, lw = 0;
            if (w < NWORDS) {
                unsigned mp = w ? mword[w - 1] : 0u;
                unsigned mc = mword[w];
                unsigned mn = mword[w + 1];       // words 118/119 are zero
                unsigned long long X = ((unsigned long long)mc << 32) | mp;
                unsigned long long z = (X << 1) | (X << 2);
                z |= z << 2; z |= z << 4; z |= z << 8;
                z |= (X << 17) | (X << 18);
                sw = mc & ~(unsigned)(z >> 32);
                unsigned long long Y = ((unsigned long long)mn << 32) | mc;
                unsigned long long q = (Y >> 1) | (Y >> 2);
                q |= q >> 2; q |= q >> 4; q |= q >> 8;
                q |= (Y >> 17) | (Y >> 18);
                lw = mc & ~(unsigned)q;
            }
            swv[j] = sw; lwv[j] = lw;
            scnt += __popc(sw); lcnt += __popc(lw);
        }
        int packed = scnt | (lcnt << 16);
        int x = warp_incl_scan(packed, lane);
        int excl = x - packed;
        if (lane == 31) G_sh = (x >> 16);
        // lasts by ordinal
        {
            int rank = excl >> 16;
            #pragma unroll
            for (int j = 0; j < 4; j++) {
                unsigned lw = lwv[j];
                int basep = (lane * 4 + j) << 5;
                while (lw) {
                    int k = __ffs(lw) - 1; lw &= lw - 1u;
                    llist[rank++] = (short)(basep + k);
                }
            }
        }
        __syncwarp();
        // starts pair with same-ordinal last
        {
            int rank = excl & 0xFFFF;
            #pragma unroll
            for (int j = 0; j < 4; j++) {
                unsigned sw = swv[j];
                int basep = (lane * 4 + j) << 5;
                while (sw) {
                    int k = __ffs(sw) - 1; sw &= sw - 1u;
                    int t = basep + k;
                    int l = llist[rank];
                    bool closed = (l + SILF <= T_ - 1);
                    int end = closed ? l : T_;   // closed end excludes the last 1 (reference)
                    bool valid = (end - t >= MINSP);
                    vs_s[rank] = (short)t;
                    ve_s[rank] = (short)(valid ? end : t);  // empty if invalid
                    rank++;
                }
            }
        }
    }
    __syncthreads();

    // ---- output: covered iff inside interval (binary search, G usually 1) ----
    int G = G_sh;
    float* orow = out + (size_t)b * T_;
    #pragma unroll
    for (int r = 0; r < 4; r++) {
        int p = r * 1024 + tid;
        if (p < T_) {
            float o = 0.0f;
            if (G > 0 && (int)vs_s[0] <= p) {
                int lo = 0, hi = G - 1;
                while (lo < hi) {
                    int mid = (lo + hi + 1) >> 1;
                    if ((int)vs_s[mid] <= p) lo = mid; else hi = mid - 1;
                }
                if (p < (int)ve_s[lo]) o = 1.0f;
            }
            orow[p] = o;
        }
    }
}

extern "C" void kernel_launch(void* const* d_in, const int* in_sizes, int n_in,
                              void* d_out, int out_size) {
    const float* W = (const float*)d_in[0];
    int n_samples = in_sizes[0] / BATCH;   // 960000
    vad_fused_kernel<<<NBLK, 1024>>>(W, (float*)d_out, n_samples);
}

// round 12
// speedup vs baseline: 1.3242x; 1.3242x over previous
#include <cuda_runtime.h>
#include <cuda_bf16.h>

#define BATCH  32
#define T_     3749            // num frames per row
#define CROW   3750            // chunks per row
#define NCHUNK (BATCH*CROW)    // 120000
#define NBLK   148
#define TILE   811             // ceil(NCHUNK/NBLK)
#define SILF   18
#define MINSP  6
#define WN32   120             // mask words storage (padded)
#define NWORDS 118             // ceil(3749/32)
#define HB1    4096            // pass-1 bins (top 12 bits)
#define MAXG   256

__device__ float    g_E[BATCH * T_];
__device__ int      g_hist[BATCH * HB1];  // zero at load; phase 2 restores zeros
__device__ int      g_nzero[BATCH];       // zero at load; phase 2 restores zeros
__device__ unsigned g_count;
__device__ unsigned g_epoch;

__device__ __forceinline__ void grid_barrier() {
    __syncthreads();
    if (threadIdx.x == 0) {
        unsigned e0 = *((volatile unsigned*)&g_epoch);
        __threadfence();
        unsigned a = atomicAdd(&g_count, 1u);
        if (a == NBLK - 1) {
            g_count = 0;
            __threadfence();
            atomicAdd(&g_epoch, 1u);
        } else {
            while (*((volatile unsigned*)&g_epoch) == e0) { }
        }
        __threadfence();
    }
    __syncthreads();
}

__device__ __forceinline__ int warp_incl_scan(int x, int lane) {
    #pragma unroll
    for (int o = 1; o < 32; o <<= 1) {
        int y = __shfl_up_sync(0xFFFFFFFFu, x, o);
        if (lane >= o) x += y;
    }
    return x;
}
__device__ __forceinline__ int block_excl_scan(int v, int lane, int wid, int* warp_sums) {
    int x = warp_incl_scan(v, lane);
    if (lane == 31) warp_sums[wid] = x;
    __syncthreads();
    if (wid == 0) {
        int ws = warp_sums[lane];
        int xx = warp_incl_scan(ws, lane);
        warp_sums[lane] = xx - ws;
    }
    __syncthreads();
    int res = warp_sums[wid] + x - v;
    __syncthreads();
    return res;
}

__global__ __launch_bounds__(1024, 1)
void vad_fused_kernel(const float* __restrict__ W, float* __restrict__ out, int n_samples) {
    int tid = threadIdx.x, lane = tid & 31, wid = tid >> 5;

    __shared__ float    s_sum[TILE + 1];
    __shared__ int      hist_s[1024];
    __shared__ unsigned mword[WN32], lword[WN32], sword[WN32];
    __shared__ int      woff[WN32];
    __shared__ short    llist[MAXG];
    __shared__ short    vs_s[MAXG];
    __shared__ short    ve_s[MAXG];
    __shared__ int      warp_sums[32];
    __shared__ unsigned mg_w[32];
    __shared__ int      r_sh;
    __shared__ unsigned prefix_sh;
    __shared__ float    thr_sh;
    __shared__ int      G_sh;

    // ===== Phase 1: depth-4 pipelined chunk sums -> energies + hist + nzero =====
    int s0   = blockIdx.x * TILE;
    int len  = min(TILE, NCHUNK - s0);
    int nsum = min(len + 1, NCHUNK - s0);

    {
        float4 a0={0,0,0,0}, b0={0,0,0,0}, a1={0,0,0,0}, b1={0,0,0,0};
        float4 a2={0,0,0,0}, b2={0,0,0,0};
        int j = wid;
        if (j < nsum) {
            int c = s0 + j; int r = c / CROW, jj = c - r * CROW;
            const float4* p = (const float4*)(W + (size_t)r * n_samples) + (size_t)jj * 64;
            a0 = __ldcs(p + lane); b0 = __ldcs(p + lane + 32);
        }
        if (j + 32 < nsum) {
            int c = s0 + j + 32; int r = c / CROW, jj = c - r * CROW;
            const float4* p = (const float4*)(W + (size_t)r * n_samples) + (size_t)jj * 64;
            a1 = __ldcs(p + lane); b1 = __ldcs(p + lane + 32);
        }
        if (j + 64 < nsum) {
            int c = s0 + j + 64; int r = c / CROW, jj = c - r * CROW;
            const float4* p = (const float4*)(W + (size_t)r * n_samples) + (size_t)jj * 64;
            a2 = __ldcs(p + lane); b2 = __ldcs(p + lane + 32);
        }
        for (; j < nsum; j += 32) {
            float4 a3={0,0,0,0}, b3={0,0,0,0};
            if (j + 96 < nsum) {
                int c = s0 + j + 96; int r = c / CROW, jj = c - r * CROW;
                const float4* p = (const float4*)(W + (size_t)r * n_samples) + (size_t)jj * 64;
                a3 = __ldcs(p + lane); b3 = __ldcs(p + lane + 32);
            }
            float v = a0.x*a0.x + a0.y*a0.y + a0.z*a0.z + a0.w*a0.w
                    + b0.x*b0.x + b0.y*b0.y + b0.z*b0.z + b0.w*b0.w;
            #pragma unroll
            for (int o = 16; o; o >>= 1) v += __shfl_down_sync(0xFFFFFFFFu, v, o);
            if (lane == 0) s_sum[j] = v;
            a0 = a1; b0 = b1; a1 = a2; b1 = b2; a2 = a3; b2 = b3;
        }
    }
    __syncthreads();

    {
        int i = tid;
        bool ok = (i < len);
        int rowbin = -1;
        if (ok) {
            int t = s0 + i;
            int r = t / CROW;
            int tl = t - r * CROW;
            if (tl < CROW - 1) {
                float e = (s_sum[i] + s_sum[i + 1]) * (1.0f / 512.0f);
                g_E[r * T_ + tl] = e;
                if (e <= 0.0f) atomicAdd(&g_nzero[r], 1);
                rowbin = r * HB1 + (int)(__float_as_uint(e) >> 20);
            }
        }
        unsigned grp = __match_any_sync(0xFFFFFFFFu, rowbin);
        if (rowbin >= 0 && lane == __ffs(grp) - 1)
            atomicAdd(&g_hist[rowbin], __popc(grp));
    }

    grid_barrier();

    // ===== Phase 2: per-row VAD, register-resident keys =====
    if (blockIdx.x >= BATCH) return;
    int b = blockIdx.x;

    hist_s[tid] = 0;

    unsigned key[4]; bool kval[4];
    const float* Erow = g_E + b * T_;
    #pragma unroll
    for (int r = 0; r < 4; r++) {
        int i = r * 1024 + tid;
        kval[r] = (i < T_);
        key[r] = kval[r] ? __float_as_uint(Erow[i]) : 0u;
    }
    int nzero = g_nzero[b];
    int h4[4]; int base4 = tid << 2;
    #pragma unroll
    for (int j = 0; j < 4; j++) {
        h4[j] = g_hist[b * HB1 + base4 + j];
        g_hist[b * HB1 + base4 + j] = 0;
    }
    __syncthreads();
    if (tid == 0) g_nzero[b] = 0;

    int nz = T_ - nzero;
    float pos  = 0.2f * (float)(nz - 1);
    float flo  = floorf(pos);
    float frac = pos - flo;
    int ilo = min(max(nzero + (int)flo, 0), T_ - 1);
    int ihi = min(max(nzero + (int)ceilf(pos), 0), T_ - 1);

    // ---- pass 1: top-12-bit bin from precomputed hist ----
    int tsum = h4[0] + h4[1] + h4[2] + h4[3];
    int texcl = block_excl_scan(tsum, lane, wid, warp_sums);
    {
        int cum = texcl;
        #pragma unroll
        for (int j = 0; j < 4; j++) {
            if (ilo >= cum && ilo < cum + h4[j]) { r_sh = ilo - cum; prefix_sh = (unsigned)(base4 + j) << 20; }
            cum += h4[j];
        }
    }
    __syncthreads();
    unsigned prefix = prefix_sh;

    // ---- pass 2: bits 19..10 (plain atomics; few participants, spread bins) ----
    #pragma unroll
    for (int r = 0; r < 4; r++) {
        if (kval[r] && ((key[r] & 0xFFF00000u) == prefix))
            atomicAdd(&hist_s[(key[r] >> 10) & 1023u], 1);
    }
    __syncthreads();
    {
        int h = hist_s[tid]; hist_s[tid] = 0;
        int rr = r_sh;
        int excl = block_excl_scan(h, lane, wid, warp_sums);
        if (rr >= excl && rr < excl + h) { r_sh = rr - excl; prefix_sh = prefix | ((unsigned)tid << 10); }
    }
    __syncthreads();
    prefix = prefix_sh;

    // ---- pass 3: bits 9..0 (plain atomics) ----
    #pragma unroll
    for (int r = 0; r < 4; r++) {
        if (kval[r] && ((key[r] & 0xFFFFFC00u) == prefix))
            atomicAdd(&hist_s[key[r] & 1023u], 1);
    }
    __syncthreads();
    {
        int h = hist_s[tid];
        int rr = r_sh;
        int excl = block_excl_scan(h, lane, wid, warp_sums);
        if (rr >= excl && rr < excl + h) prefix_sh = prefix | (unsigned)tid;
    }
    __syncthreads();
    prefix = prefix_sh;
    float v_lo = __uint_as_float(prefix);

    // ---- cle/mingt via warp arrays ----
    {
        int cle = 0;
        unsigned mingt = 0xFFFFFFFFu;
        #pragma unroll
        for (int r = 0; r < 4; r++) {
            if (kval[r]) {
                if (key[r] <= prefix) cle++;
                else mingt = min(mingt, key[r]);
            }
        }
        #pragma unroll
        for (int o = 16; o; o >>= 1) {
            cle  += __shfl_down_sync(0xFFFFFFFFu, cle, o);
            mingt = min(mingt, __shfl_down_sync(0xFFFFFFFFu, mingt, o));
        }
        if (lane == 0) { warp_sums[wid] = cle; mg_w[wid] = mingt; }
        __syncthreads();
        if (wid == 0) {
            int c = warp_sums[lane];
            unsigned m = mg_w[lane];
            #pragma unroll
            for (int o = 16; o; o >>= 1) {
                c += __shfl_down_sync(0xFFFFFFFFu, c, o);
                m = min(m, __shfl_down_sync(0xFFFFFFFFu, m, o));
            }
            if (lane == 0) {
                float v_hi = (c > ihi) ? v_lo : __uint_as_float(m);
                float thr  = v_lo * (1.0f - frac) + v_hi * frac;
                thr_sh = (nz > 0) ? thr : 0.01f;
            }
        }
        __syncthreads();
    }
    float thr = thr_sh;

    // ---- mask ballot from register keys ----
    #pragma unroll
    for (int r = 0; r < 4; r++) {
        int i = r * 1024 + tid;
        bool pred = kval[r] && (__uint_as_float(key[r]) > thr);
        unsigned w = __ballot_sync(0xFFFFFFFFu, pred);
        if (lane == 0 && (i >> 5) < WN32) mword[i >> 5] = w;
    }
    __syncthreads();

    // ---- word-parallel start/last flags via 64-bit window-OR ----
    int cnt = 0;
    if (tid < NWORDS) {
        unsigned mp = tid ? mword[tid - 1] : 0u;
        unsigned mc = mword[tid];
        unsigned mn = mword[tid + 1];   // words 118/119 are zero
        unsigned long long X = ((unsigned long long)mc << 32) | mp;
        unsigned long long z = (X << 1) | (X << 2);
        z |= z << 2; z |= z << 4; z |= z << 8;
        z |= (X << 17) | (X << 18);
        unsigned sw = mc & ~(unsigned)(z >> 32);
        unsigned long long Y = ((unsigned long long)mn << 32) | mc;
        unsigned long long q = (Y >> 1) | (Y >> 2);
        q |= q >> 2; q |= q >> 4; q |= q >> 8;
        q |= (Y >> 17) | (Y >> 18);
        unsigned lw = mc & ~(unsigned)q;
        sword[tid] = sw; lword[tid] = lw;
        cnt = __popc(sw) | (__popc(lw) << 16);
    }
    {
        int excl = block_excl_scan(cnt, lane, wid, warp_sums);
        if (tid < NWORDS) woff[tid] = excl;
        if (tid == NWORDS - 1) G_sh = (excl + cnt) & 0xFFFF;
    }
    __syncthreads();

    // lasts write positions by ordinal
    if (tid < NWORDS) {
        unsigned lw = lword[tid];
        int rank = woff[tid] >> 16;
        int basep = tid << 5;
        while (lw) {
            int k = __ffs(lw) - 1; lw &= lw - 1u;
            llist[rank++] = (short)(basep + k);
        }
    }
    __syncthreads();

    // starts pair with same-ordinal last; emit compact sorted intervals
    if (tid < NWORDS) {
        unsigned sw = sword[tid];
        int rank = woff[tid] & 0xFFFF;
        int basep = tid << 5;
        while (sw) {
            int k = __ffs(sw) - 1; sw &= sw - 1u;
            int t = basep + k;
            int l = llist[rank];
            bool closed = (l + SILF <= T_ - 1);
            int end = closed ? l : T_;      // closed end excludes the last 1 (reference)
            bool valid = (end - t >= MINSP);
            vs_s[rank] = (short)t;
            ve_s[rank] = (short)(valid ? end : t);   // empty interval if invalid
            rank++;
        }
    }
    __syncthreads();

    // ---- output: covered iff inside interval (binary search, G usually 1) ----
    int G = G_sh;
    float* orow = out + (size_t)b * T_;
    #pragma unroll
    for (int r = 0; r < 4; r++) {
        int p = r * 1024 + tid;
        if (p < T_) {
            float o = 0.0f;
            if (G > 0 && (int)vs_s[0] <= p) {
                int lo = 0, hi = G - 1;
                while (lo < hi) {
                    int mid = (lo + hi + 1) >> 1;
                    if ((int)vs_s[mid] <= p) lo = mid; else hi = mid - 1;
                }
                if (p < (int)ve_s[lo]) o = 1.0f;
            }
            orow[p] = o;
        }
    }
}

extern "C" void kernel_launch(void* const* d_in, const int* in_sizes, int n_in,
                              void* d_out, int out_size) {
    const float* W = (const float*)d_in[0];
    int n_samples = in_sizes[0] / BATCH;   // 960000
    vad_fused_kernel<<<NBLK, 1024>>>(W, (float*)d_out, n_samples);
}